// round 1
// baseline (speedup 1.0000x reference)
#include <cuda_runtime.h>
#include <cstdint>

// Correlation1D: out[b,d,h,w] = (1/256) * sum_c in1[b,c,h,w] * in2pad[b,c,h,w+d]
// in2 zero-padded by 40 on each side of W; d in [0,81), disp = d-40.
// Shapes: in1,in2 [8,256,96,192] f32; out [8,81,96,192] f32.

#define Bn 8
#define Cn 256
#define Hn 96
#define Wn 192
#define Dn 81
#define PADn 40

#define WT 96        // w columns per block (2 blocks cover W=192)
#define TD 11        // d per thread (8 groups * 11 = 88 >= 81)
#define TW 4         // w per thread
#define NDG 8        // d groups
#define NWG 24       // w groups (24*4 = 96)
#define NTHREADS 192
#define CT 16        // channels per smem stage
#define CP 8         // channel-pairs per stage
#define NSTAGE (Cn / CT)
#define BU 184       // B smem width in u = w_intile + d (0..182, padded to 184)

__global__ __launch_bounds__(NTHREADS, 2)
void corr1d_kernel(const float* __restrict__ in1,
                   const float* __restrict__ in2,
                   float* __restrict__ out) {
    __shared__ __align__(16) float2 A2[CP][WT];   // [cpair][w]  (.x = even c, .y = odd c)
    __shared__ __align__(16) float2 B2[CP][BU];   // [cpair][u],  u = w_intile + d

    const int w0  = blockIdx.x * WT;   // 0 or 96
    const int h   = blockIdx.y;
    const int b   = blockIdx.z;
    const int tid = threadIdx.x;
    const int dg  = tid & 7;           // d group: fastest within warp -> stride-11 smem addrs
    const int wg  = tid >> 3;          // w group 0..23

    const size_t HW = (size_t)Hn * Wn;
    const float* a_base = in1 + ((size_t)b * Cn) * HW + (size_t)h * Wn + w0;
    const float* b_base = in2 + ((size_t)b * Cn) * HW + (size_t)h * Wn;

    // f32x2 packed accumulators: lo = even channels, hi = odd channels
    unsigned long long acc[TD][TW];
#pragma unroll
    for (int t = 0; t < TD; ++t)
#pragma unroll
        for (int i = 0; i < TW; ++i) acc[t][i] = 0ull;

    // Static A-load task for this thread (192 tasks: 8 cpairs x 24 float4-groups)
    const int a_cp = tid / NWG;      // 0..7
    const int a_w4 = tid % NWG;      // 0..23

    for (int stage = 0; stage < NSTAGE; ++stage) {
        const int cbase = stage * CT;
        __syncthreads();  // previous stage's compute done before overwrite

        // ---- load A tile: 16 channels x 96 w, interleaved into float2 pairs ----
        {
            const float* g0 = a_base + (size_t)(cbase + 2 * a_cp) * HW + a_w4 * 4;
            float4 r0 = *(const float4*)g0;
            float4 r1 = *(const float4*)(g0 + HW);
            float4* dst = (float4*)&A2[a_cp][a_w4 * 4];
            dst[0] = make_float4(r0.x, r1.x, r0.y, r1.y);
            dst[1] = make_float4(r0.z, r1.z, r0.w, r1.w);
        }

        // ---- load B tile: 16 channels x 184 u, with zero padding outside [0,W) ----
        for (int task = tid; task < CP * 46; task += NTHREADS) {
            const int cp = task / 46;
            const int u4 = task % 46;
            const int wp = w0 - PADn + u4 * 4;   // global w' of first element (mult of 4)
            const float* g0 = b_base + (size_t)(cbase + 2 * cp) * HW + wp;
            const float* g1 = g0 + HW;
            float4 r0, r1;
            if (wp >= 0 && wp + 3 < Wn) {
                r0 = *(const float4*)g0;
                r1 = *(const float4*)g1;
            } else {
                float v0[4], v1[4];
#pragma unroll
                for (int k = 0; k < 4; ++k) {
                    const int wk = wp + k;
                    const bool ok = (wk >= 0) && (wk < Wn);
                    v0[k] = ok ? g0[k] : 0.0f;
                    v1[k] = ok ? g1[k] : 0.0f;
                }
                r0 = make_float4(v0[0], v0[1], v0[2], v0[3]);
                r1 = make_float4(v1[0], v1[1], v1[2], v1[3]);
            }
            float4* dst = (float4*)&B2[cp][u4 * 4];
            dst[0] = make_float4(r0.x, r1.x, r0.y, r1.y);
            dst[1] = make_float4(r0.z, r1.z, r0.w, r1.w);
        }
        __syncthreads();

        // ---- compute: 8 channel-pairs, per-thread 4w x 11d register tile ----
#pragma unroll
        for (int cp = 0; cp < CP; ++cp) {
            unsigned long long a[TW];
            unsigned long long bw[TD + TW - 1];
            const int wbase = wg * TW;
            const int ubase = wbase + dg * TD;
#pragma unroll
            for (int i = 0; i < TW; ++i)
                a[i] = *(const unsigned long long*)&A2[cp][wbase + i];
#pragma unroll
            for (int j = 0; j < TD + TW - 1; ++j)
                bw[j] = *(const unsigned long long*)&B2[cp][ubase + j];
#pragma unroll
            for (int t = 0; t < TD; ++t)
#pragma unroll
                for (int i = 0; i < TW; ++i)
                    asm("fma.rn.f32x2 %0, %1, %2, %0;"
                        : "+l"(acc[t][i])
                        : "l"(a[i]), "l"(bw[t + i]));
        }
    }

    // ---- epilogue: fold packed halves, scale by 1/C, store ----
    const float scale = 1.0f / (float)Cn;
#pragma unroll
    for (int t = 0; t < TD; ++t) {
        const int d = dg * TD + t;
        if (d < Dn) {
#pragma unroll
            for (int i = 0; i < TW; ++i) {
                const int w = w0 + wg * TW + i;
                const float lo = __uint_as_float((unsigned)acc[t][i]);
                const float hi = __uint_as_float((unsigned)(acc[t][i] >> 32));
                out[(((size_t)b * Dn + d) * Hn + h) * Wn + w] = (lo + hi) * scale;
            }
        }
    }
}

extern "C" void kernel_launch(void* const* d_in, const int* in_sizes, int n_in,
                              void* d_out, int out_size) {
    const float* in1 = (const float*)d_in[0];
    const float* in2 = (const float*)d_in[1];
    float* out = (float*)d_out;
    dim3 grid(Wn / WT, Hn, Bn);   // (2, 96, 8)
    dim3 block(NTHREADS);
    corr1d_kernel<<<grid, block>>>(in1, in2, out);
}

// round 3
// speedup vs baseline: 2.4701x; 2.4701x over previous
#include <cuda_runtime.h>
#include <cuda_bf16.h>
#include <cstdint>

// Correlation1D as a band-GEMM using mma.sync (HMMA) with 3x bf16 passes
// emulating fp32 (hi/lo split): out[b,d,h,w] = (1/256)*sum_c in1[b,c,h,w]*in2pad[b,c,h,w+d]
// Shapes: in1,in2 [8,256,96,192] f32; out [8,81,96,192] f32.
//
// Per CTA = one (b,h): D[w,u] = sum_c A[c,w]*B[c,u], band d = u - w in [0,81).
// 12 warps, warp wid owns m-tile w0 = wid*16; n-tiles u0 = w0 + nt*8, nt=0..11.

#define Bn 8
#define Cn 256
#define Hn 96
#define Wn 192
#define Dn 81
#define PADn 40
#define HWn (Hn * Wn)

#define NTHREADS 384
#define KC 32                    // channels per chunk
#define NCHUNK (Cn / KC)         // 8
#define AROWS 192
#define BROWS 272
#define ROWB 128                 // [hi 32ch = 64B | lo 32ch = 64B]
#define ABYTES (AROWS * ROWB)    // 24576
#define BBYTES (BROWS * ROWB)    // 34816
#define OUTT_BYTES (Dn * Wn * 4) // 62208
#define DYNSMEM 63488

#define SW128(o) ((unsigned)(o) ^ ((((unsigned)(o)) >> 3) & 0x70))

static __device__ __forceinline__ uint32_t smem_u32(const void* p) {
    uint32_t a;
    asm("{ .reg .u64 t; cvta.to.shared.u64 t, %1; cvt.u32.u64 %0, t; }" : "=r"(a) : "l"(p));
    return a;
}

// Convert 8 consecutive-channel fp32 values to bf16 hi|lo, store swizzled.
static __device__ __forceinline__ void cvt_store8(char* tile, int row, int g,
                                                  const float* src, bool ok) {
    float v[8];
#pragma unroll
    for (int k = 0; k < 8; ++k) v[k] = ok ? src[(size_t)k * HWn] : 0.0f;
    unsigned hu[4], lu[4];
#pragma unroll
    for (int k = 0; k < 4; ++k) {
        __nv_bfloat16 h0 = __float2bfloat16(v[2 * k]);
        __nv_bfloat16 h1 = __float2bfloat16(v[2 * k + 1]);
        __nv_bfloat16 l0 = __float2bfloat16(v[2 * k] - __bfloat162float(h0));
        __nv_bfloat16 l1 = __float2bfloat16(v[2 * k + 1] - __bfloat162float(h1));
        hu[k] = (unsigned)__bfloat16_as_ushort(h0) | ((unsigned)__bfloat16_as_ushort(h1) << 16);
        lu[k] = (unsigned)__bfloat16_as_ushort(l0) | ((unsigned)__bfloat16_as_ushort(l1) << 16);
    }
    unsigned off = (unsigned)(row * ROWB + 16 * g);
    *(uint4*)(tile + SW128(off)) = make_uint4(hu[0], hu[1], hu[2], hu[3]);
    *(uint4*)(tile + SW128(off + 64)) = make_uint4(lu[0], lu[1], lu[2], lu[3]);
}

__global__ __launch_bounds__(NTHREADS, 2)
void corr1d_mma_kernel(const float* __restrict__ in1,
                       const float* __restrict__ in2,
                       float* __restrict__ out) {
    extern __shared__ char dsm_raw[];
    const uint32_t dsm_addr = smem_u32(dsm_raw);
    const uint32_t base_addr = (dsm_addr + 1023u) & ~1023u;
    char* smp = dsm_raw + (base_addr - dsm_addr);

    const int h = blockIdx.x;
    const int b = blockIdx.y;
    const int tid = threadIdx.x;
    const int wid = tid >> 5;
    const int lane = tid & 31;

    const float* a_src = in1 + (size_t)b * Cn * HWn + (size_t)h * Wn;
    const float* b_src = in2 + (size_t)b * Cn * HWn + (size_t)h * Wn;

    char* At = smp;
    char* Bt = smp + ABYTES;
    const uint32_t At_u = base_addr;
    const uint32_t Bt_u = base_addr + ABYTES;

    float acc[12][4];
#pragma unroll
    for (int n = 0; n < 12; ++n)
#pragma unroll
        for (int i = 0; i < 4; ++i) acc[n][i] = 0.0f;

    const int w0 = wid * 16;
    // ldmatrix lane-address components (constant across chunks)
    const int a_row = w0 + (lane & 15);
    const int a_k16 = (lane >> 4) * 16;       // 0 or 16 bytes (k0-7 vs k8-15)
    const int b_row_off = lane & 7;
    const int b_k16 = ((lane >> 3) & 1) * 16;

    for (int ch = 0; ch < NCHUNK; ++ch) {
        const int c0 = ch * KC;
        __syncthreads();   // previous chunk's compute finished before overwrite

        // ---- load + convert A: 192 rows x 4 groups of 8 channels ----
#pragma unroll
        for (int it = 0; it < 2; ++it) {
            const int t = tid + it * NTHREADS;           // 768 tasks
            const int w = t % AROWS;
            const int g = t / AROWS;
            cvt_store8(At, w, g, a_src + (size_t)(c0 + 8 * g) * HWn + w, true);
        }
        // ---- load + convert B: 272 rows x 4 groups; u -> col u-40, zero-pad ----
        for (int t = tid; t < BROWS * 4; t += NTHREADS) {  // 1088 tasks
            const int u = t % BROWS;
            const int g = t / BROWS;
            const int col = u - PADn;
            const bool ok = (col >= 0) && (col < Wn);
            cvt_store8(Bt, u, g, b_src + (size_t)(c0 + 8 * g) * HWn + col, ok);
        }
        __syncthreads();

        // ---- compute: 2 k-steps x 3 passes x 12 n-tiles ----
#pragma unroll
        for (int ks = 0; ks < 2; ++ks) {
#pragma unroll
            for (int p = 0; p < 3; ++p) {
                const int aoff = (p == 2) ? 64 : 0;   // A: hi,hi,lo
                const int boff = (p == 1) ? 64 : 0;   // B: hi,lo,hi
                uint32_t a0, a1, a2, a3;
                {
                    const uint32_t addrA =
                        At_u + SW128(a_row * ROWB + aoff + ks * 32 + a_k16);
                    asm volatile(
                        "ldmatrix.sync.aligned.m8n8.x4.shared.b16 {%0,%1,%2,%3}, [%4];"
                        : "=r"(a0), "=r"(a1), "=r"(a2), "=r"(a3) : "r"(addrA));
                }
#pragma unroll
                for (int nt = 0; nt < 12; ++nt) {
                    uint32_t b0, b1;
                    const uint32_t addrB =
                        Bt_u + SW128((w0 + nt * 8 + b_row_off) * ROWB + boff + ks * 32 + b_k16);
                    asm volatile(
                        "ldmatrix.sync.aligned.m8n8.x2.shared.b16 {%0,%1}, [%2];"
                        : "=r"(b0), "=r"(b1) : "r"(addrB));
                    asm volatile(
                        "mma.sync.aligned.m16n8k16.row.col.f32.bf16.bf16.f32 "
                        "{%0,%1,%2,%3}, {%4,%5,%6,%7}, {%8,%9}, {%0,%1,%2,%3};"
                        : "+f"(acc[nt][0]), "+f"(acc[nt][1]), "+f"(acc[nt][2]), "+f"(acc[nt][3])
                        : "r"(a0), "r"(a1), "r"(a2), "r"(a3), "r"(b0), "r"(b1));
                }
            }
        }
    }

    // ---- epilogue: band extraction into smem, then coalesced store ----
    __syncthreads();           // all compute done; smem tiles dead
    float* outT = (float*)smp; // [81][192] f32
    const float scale = 1.0f / (float)Cn;
    const int r_ = lane >> 2;
    const int col2 = (lane & 3) * 2;
#pragma unroll
    for (int nt = 0; nt < 12; ++nt) {
#pragma unroll
        for (int half = 0; half < 2; ++half) {
            const int mrow = r_ + half * 8;
            const int w = w0 + mrow;
#pragma unroll
            for (int e = 0; e < 2; ++e) {
                const int d = nt * 8 + col2 + e - mrow;
                if (d >= 0 && d < Dn) {
                    outT[d * Wn + w] = acc[nt][half * 2 + e] * scale;
                }
            }
        }
    }
    __syncthreads();

    for (int t = tid; t < Dn * (Wn / 4); t += NTHREADS) {
        const int d = t / (Wn / 4);
        const int q = t % (Wn / 4);
        const float4 v = ((const float4*)outT)[d * (Wn / 4) + q];
        *(float4*)(out + (((size_t)b * Dn + d) * Hn + h) * Wn + q * 4) = v;
    }
}

extern "C" void kernel_launch(void* const* d_in, const int* in_sizes, int n_in,
                              void* d_out, int out_size) {
    const float* in1 = (const float*)d_in[0];
    const float* in2 = (const float*)d_in[1];
    float* out = (float*)d_out;
    cudaFuncSetAttribute(corr1d_mma_kernel, cudaFuncAttributeMaxDynamicSharedMemorySize, DYNSMEM);
    dim3 grid(Hn, Bn);   // (96, 8)
    corr1d_mma_kernel<<<grid, NTHREADS, DYNSMEM>>>(in1, in2, out);
}

// round 4
// speedup vs baseline: 3.1954x; 1.2936x over previous
#include <cuda_runtime.h>
#include <cuda_bf16.h>
#include <cstdint>

// Correlation1D band-GEMM: mma.sync bf16 3-pass fp32 emulation, with a
// cp.async double-buffered pipeline decoupling DRAM streaming from compute.
// out[b,d,h,w] = (1/256)*sum_c in1[b,c,h,w]*in2pad[b,c,h,w+d-40]
// in1,in2 [8,256,96,192] f32; out [8,81,96,192] f32.

#define Bn 8
#define Cn 256
#define Hn 96
#define Wn 192
#define Dn 81
#define PADn 40
#define HWn (Hn * Wn)

#define NTHREADS 384
#define KC 16                     // channels per chunk
#define NCHUNK (Cn / KC)          // 16
#define AROWS 192
#define BROWS 272

// fp32 staging (row-padded for conflict-free transpose reads)
#define STA_ROWF 196              // floats per A stage row (192 used)
#define STB_ROWF 276              // floats per B stage row (272 slots, 192 valid)
#define STA_BYTES (KC * STA_ROWF * 4)   // 12544
#define STB_BYTES (KC * STB_ROWF * 4)   // 17664
#define STAGE_BYTES (STA_BYTES + STB_BYTES) // 30208

// bf16 tiles: row = [hi 16ch = 32B | lo 32B]
#define ROWB 64
#define TA_BYTES (AROWS * ROWB)   // 12288
#define TB_BYTES (BROWS * ROWB)   // 17408

#define OFF_STAGE0 0
#define OFF_STAGE1 STAGE_BYTES
#define OFF_TILEA (2 * STAGE_BYTES)            // 60416
#define OFF_TILEB (OFF_TILEA + TA_BYTES)       // 72704
#define SMEM_USED (OFF_TILEB + TB_BYTES)       // 90112
#define DYNSMEM (SMEM_USED + 1024)

// per-row XOR swizzle for 64B rows, 16B granularity
#define SWX(row, koff) ((unsigned)(koff) ^ ((((unsigned)(row) >> 1) & 3u) << 4))

static __device__ __forceinline__ uint32_t smem_u32(const void* p) {
    uint32_t a;
    asm("{ .reg .u64 t; cvta.to.shared.u64 t, %1; cvt.u32.u64 %0, t; }" : "=r"(a) : "l"(p));
    return a;
}

static __device__ __forceinline__ void cp_async16(uint32_t dst, const void* src) {
    asm volatile("cp.async.cg.shared.global [%0], [%1], 16;" :: "r"(dst), "l"(src) : "memory");
}

// convert 8 fp32 (from regs) to bf16 hi|lo 16B units, store swizzled
static __device__ __forceinline__ void cvt8_store(char* tile, int row, int g,
                                                  const float* v) {
    unsigned hu[4], lu[4];
#pragma unroll
    for (int k = 0; k < 4; ++k) {
        __nv_bfloat16 h0 = __float2bfloat16(v[2 * k]);
        __nv_bfloat16 h1 = __float2bfloat16(v[2 * k + 1]);
        __nv_bfloat16 l0 = __float2bfloat16(v[2 * k] - __bfloat162float(h0));
        __nv_bfloat16 l1 = __float2bfloat16(v[2 * k + 1] - __bfloat162float(h1));
        hu[k] = (unsigned)__bfloat16_as_ushort(h0) | ((unsigned)__bfloat16_as_ushort(h1) << 16);
        lu[k] = (unsigned)__bfloat16_as_ushort(l0) | ((unsigned)__bfloat16_as_ushort(l1) << 16);
    }
    char* rowp = tile + row * ROWB;
    *(uint4*)(rowp + SWX(row, 16 * g)) = make_uint4(hu[0], hu[1], hu[2], hu[3]);
    *(uint4*)(rowp + SWX(row, 32 + 16 * g)) = make_uint4(lu[0], lu[1], lu[2], lu[3]);
}

__global__ __launch_bounds__(NTHREADS, 2)
void corr1d_pipe_kernel(const float* __restrict__ in1,
                        const float* __restrict__ in2,
                        float* __restrict__ out) {
    extern __shared__ char dsm_raw[];
    const uint32_t dsm_addr = smem_u32(dsm_raw);
    const uint32_t base_u = (dsm_addr + 1023u) & ~1023u;
    char* smp = dsm_raw + (base_u - dsm_addr);

    const int h = blockIdx.x;
    const int b = blockIdx.y;
    const int tid = threadIdx.x;
    const int wid = tid >> 5;
    const int lane = tid & 31;

    const float* a_src = in1 + (size_t)b * Cn * HWn + (size_t)h * Wn;
    const float* b_src = in2 + (size_t)b * Cn * HWn + (size_t)h * Wn;

    char* tileA = smp + OFF_TILEA;
    char* tileB = smp + OFF_TILEB;
    const uint32_t tileA_u = base_u + OFF_TILEA;
    const uint32_t tileB_u = base_u + OFF_TILEB;

    // ---- pre-zero the OOB u-regions of both B stages (cols <40 and >=232) ----
    for (int t = tid; t < 2 * KC * 80; t += NTHREADS) {
        const int s = t / (KC * 80);
        const int r = (t % (KC * 80)) / 80;
        const int j = t % 80;
        const int u = (j < 40) ? j : (232 + j - 40);
        *(float*)(smp + (s ? OFF_STAGE1 : OFF_STAGE0) + STA_BYTES +
                  r * (STB_ROWF * 4) + 4 * u) = 0.0f;
    }

    float acc[12][4];
#pragma unroll
    for (int n = 0; n < 12; ++n)
#pragma unroll
        for (int i = 0; i < 4; ++i) acc[n][i] = 0.0f;

    const int w0 = wid * 16;
    // ldmatrix lane addressing (constant)
    const int a_row = w0 + (lane & 15);
    const int a_k16 = (lane >> 4) * 16;
    const int b_rowoff = (lane & 7) + ((lane >> 4) & 1) * 8;
    const int b_k16 = ((lane >> 3) & 1) * 16;

    // issue cp.async for a chunk into stage s
    auto issue = [&](int ch, int s) {
        const int c0 = ch * KC;
        const uint32_t stA = base_u + (s ? OFF_STAGE1 : OFF_STAGE0);
        const uint32_t stB = stA + STA_BYTES;
#pragma unroll
        for (int i = 0; i < 4; ++i) {
            int op = tid + i * NTHREADS;          // 0..1535
            if (op < 768) {
                const int k = op / 48, q = op % 48;
                cp_async16(stA + k * (STA_ROWF * 4) + q * 16,
                           a_src + (size_t)(c0 + k) * HWn + 4 * q);
            } else {
                op -= 768;
                const int k = op / 48, q = op % 48;
                cp_async16(stB + k * (STB_ROWF * 4) + 160 + q * 16,
                           b_src + (size_t)(c0 + k) * HWn + 4 * q);
            }
        }
        asm volatile("cp.async.commit_group;" ::: "memory");
    };

    issue(0, 0);

    for (int ch = 0; ch < NCHUNK; ++ch) {
        const int s = ch & 1;
        if (ch + 1 < NCHUNK) {
            issue(ch + 1, s ^ 1);
            asm volatile("cp.async.wait_group 1;" ::: "memory");
        } else {
            asm volatile("cp.async.wait_group 0;" ::: "memory");
        }
        __syncthreads();   // stage s visible to all threads

        // ---- convert pass: stage (fp32, [k][col]) -> bf16 tiles ([row][k hi|lo]) ----
        const char* stA = smp + (s ? OFF_STAGE1 : OFF_STAGE0);
        const char* stB = stA + STA_BYTES;
        {
            // A: 384 tasks = 192 w x 2 groups of 8 channels
            const int w = tid % AROWS;
            const int g = tid / AROWS;
            float v[8];
#pragma unroll
            for (int j = 0; j < 8; ++j)
                v[j] = *(const float*)(stA + (8 * g + j) * (STA_ROWF * 4) + 4 * w);
            cvt8_store(tileA, w, g, v);
        }
        for (int t = tid; t < BROWS * 2; t += NTHREADS) {   // 544 tasks
            const int u = t % BROWS;
            const int g = t / BROWS;
            float v[8];
#pragma unroll
            for (int j = 0; j < 8; ++j)
                v[j] = *(const float*)(stB + (8 * g + j) * (STB_ROWF * 4) + 4 * u);
            cvt8_store(tileB, u, g, v);
        }
        __syncthreads();   // tiles ready

        // ---- compute: A hi/lo fragments once, 6 paired-nt B x4 loads ----
        uint32_t ah[4], al[4];
        {
            const uint32_t addr = tileA_u + a_row * ROWB + SWX(a_row, a_k16);
            asm volatile("ldmatrix.sync.aligned.m8n8.x4.shared.b16 {%0,%1,%2,%3}, [%4];"
                         : "=r"(ah[0]), "=r"(ah[1]), "=r"(ah[2]), "=r"(ah[3]) : "r"(addr));
        }
        {
            const uint32_t addr = tileA_u + a_row * ROWB + SWX(a_row, 32 + a_k16);
            asm volatile("ldmatrix.sync.aligned.m8n8.x4.shared.b16 {%0,%1,%2,%3}, [%4];"
                         : "=r"(al[0]), "=r"(al[1]), "=r"(al[2]), "=r"(al[3]) : "r"(addr));
        }
#pragma unroll
        for (int ntp = 0; ntp < 6; ++ntp) {
            const int ub = w0 + ntp * 16 + b_rowoff;
            uint32_t bh[4], bl[4];
            {
                const uint32_t addr = tileB_u + ub * ROWB + SWX(ub, b_k16);
                asm volatile("ldmatrix.sync.aligned.m8n8.x4.shared.b16 {%0,%1,%2,%3}, [%4];"
                             : "=r"(bh[0]), "=r"(bh[1]), "=r"(bh[2]), "=r"(bh[3]) : "r"(addr));
            }
            {
                const uint32_t addr = tileB_u + ub * ROWB + SWX(ub, 32 + b_k16);
                asm volatile("ldmatrix.sync.aligned.m8n8.x4.shared.b16 {%0,%1,%2,%3}, [%4];"
                             : "=r"(bl[0]), "=r"(bl[1]), "=r"(bl[2]), "=r"(bl[3]) : "r"(addr));
            }
#pragma unroll
            for (int t2 = 0; t2 < 2; ++t2) {
                const int nt = ntp * 2 + t2;
                float* a4 = acc[nt];
                const uint32_t bh0 = bh[2 * t2], bh1 = bh[2 * t2 + 1];
                const uint32_t bl0 = bl[2 * t2], bl1 = bl[2 * t2 + 1];
                asm volatile("mma.sync.aligned.m16n8k16.row.col.f32.bf16.bf16.f32 "
                    "{%0,%1,%2,%3}, {%4,%5,%6,%7}, {%8,%9}, {%0,%1,%2,%3};"
                    : "+f"(a4[0]), "+f"(a4[1]), "+f"(a4[2]), "+f"(a4[3])
                    : "r"(ah[0]), "r"(ah[1]), "r"(ah[2]), "r"(ah[3]), "r"(bh0), "r"(bh1));
                asm volatile("mma.sync.aligned.m16n8k16.row.col.f32.bf16.bf16.f32 "
                    "{%0,%1,%2,%3}, {%4,%5,%6,%7}, {%8,%9}, {%0,%1,%2,%3};"
                    : "+f"(a4[0]), "+f"(a4[1]), "+f"(a4[2]), "+f"(a4[3])
                    : "r"(ah[0]), "r"(ah[1]), "r"(ah[2]), "r"(ah[3]), "r"(bl0), "r"(bl1));
                asm volatile("mma.sync.aligned.m16n8k16.row.col.f32.bf16.bf16.f32 "
                    "{%0,%1,%2,%3}, {%4,%5,%6,%7}, {%8,%9}, {%0,%1,%2,%3};"
                    : "+f"(a4[0]), "+f"(a4[1]), "+f"(a4[2]), "+f"(a4[3])
                    : "r"(al[0]), "r"(al[1]), "r"(al[2]), "r"(al[3]), "r"(bh0), "r"(bh1));
            }
        }
        __syncthreads();   // compute done before next convert overwrites tiles
    }

    // ---- epilogue: band extraction into smem, then coalesced store ----
    float* outT = (float*)smp;  // [81][192] f32, reuses stage/tile space
    const float scale = 1.0f / (float)Cn;
    const int r_ = lane >> 2;
    const int col2 = (lane & 3) * 2;
#pragma unroll
    for (int nt = 0; nt < 12; ++nt) {
#pragma unroll
        for (int half = 0; half < 2; ++half) {
            const int mrow = r_ + half * 8;
            const int w = w0 + mrow;
#pragma unroll
            for (int e = 0; e < 2; ++e) {
                const int d = nt * 8 + col2 + e - mrow;
                if (d >= 0 && d < Dn) {
                    outT[d * Wn + w] = acc[nt][half * 2 + e] * scale;
                }
            }
        }
    }
    __syncthreads();

    for (int t = tid; t < Dn * (Wn / 4); t += NTHREADS) {
        const int d = t / (Wn / 4);
        const int q = t % (Wn / 4);
        const float4 v = ((const float4*)outT)[d * (Wn / 4) + q];
        *(float4*)(out + (((size_t)b * Dn + d) * Hn + h) * Wn + q * 4) = v;
    }
}

extern "C" void kernel_launch(void* const* d_in, const int* in_sizes, int n_in,
                              void* d_out, int out_size) {
    const float* in1 = (const float*)d_in[0];
    const float* in2 = (const float*)d_in[1];
    float* out = (float*)d_out;
    cudaFuncSetAttribute(corr1d_pipe_kernel, cudaFuncAttributeMaxDynamicSharedMemorySize, DYNSMEM);
    dim3 grid(Hn, Bn);   // (96, 8)
    corr1d_pipe_kernel<<<grid, NTHREADS, DYNSMEM>>>(in1, in2, out);
}